// round 7
// baseline (speedup 1.0000x reference)
#include <cuda_runtime.h>
#include <cuda_fp16.h>
#include <math.h>

// ---------------- problem constants ----------------
namespace {
constexpr int N   = 10000;
constexpr int E   = 160000;
constexpr int C   = 64;
constexpr int LM  = 9;
constexpr int SHP = 12;          // padded sh stride (16B aligned)
constexpr int CAP = 64;          // bucket capacity (max degree ~40 for Poisson(16))
constexpr float RMAX    = 5.0f;
constexpr float INV_AVG = 1.0f / 16.0f;
constexpr float S3      = 1.7320508f;
constexpr float PI_F    = 3.14159265358979f;
constexpr float PREF    = 0.63245553203f; // sqrt(2/RMAX)
}

// ---------------- device scratch (static, no allocation) ----------------
__device__ float  g_h [N * C];
__device__ float  g_h1[N * C];
__device__ float  g_sc[N * C];
__device__ float  g_q [N * C];
__device__ float  g_shb[(size_t)N * CAP * SHP];  // bucket-ordered sh
__device__ __half g_tb [(size_t)N * CAP * C];    // bucket-ordered t = R*h1[send]
__device__ __half g_Rh [(size_t)E * C];
__device__ int    g_cnt[N];
__device__ int    g_pos[E];                      // edge -> bucket slot (n*CAP+slot)
__device__ int    g_send[E];

// ---------------- kernels ----------------

// zero counters + output bins, embed h
__global__ void k_prep(const float* __restrict__ W_embed,
                       const int* __restrict__ types,
                       float* __restrict__ out, int out_size) {
    int i = blockIdx.x * blockDim.x + threadIdx.x;
    if (i < N * C) {
        int n = i >> 6, c = i & 63;
        g_h[i] = W_embed[types[n] * C + c];
    }
    if (i < N) g_cnt[i] = 0;
    if (i < out_size) out[i] = 0.0f;
}

// Fused: per-edge geometry (sh -> bucket slot), bucket bookkeeping, radial
// Bessel basis, radial MLP R = silu(ef@W1+b)@W2 (kept in regs), then
// t0 = R * h1_layer0[sender] written bucket-ordered as fp16; R also stored
// fp16 for layer 1. 256 threads / 128 edges; 4x8 register-blocked GEMMs.
__global__ __launch_bounds__(256) void k_edge_radial(
    const float* __restrict__ pos, const int* __restrict__ ei,
    const float* __restrict__ W1, const float* __restrict__ b1,
    const float* __restrict__ W2)
{
    __shared__ float sW1[8 * 64];
    __shared__ float sB[64];
    __shared__ float sW2[64 * 64];
    __shared__ float sEfT[8 * 128];     // [k][edge]
    __shared__ float sHidT[64 * 128];   // [hidden][edge]
    __shared__ int   sPos[128];
    __shared__ int   sSend[128];

    int tid = threadIdx.x;
    int e0 = blockIdx.x * 128;
    int el = tid & 127;
    int e = e0 + el;

    for (int i = tid; i < 512; i += 256) sW1[i] = W1[i];
    if (tid < 64) sB[tid] = b1[tid];
    for (int i = tid; i < 4096; i += 256) sW2[i] = W2[i];

    // geometry (computed redundantly by the 2 thread-slices; cheap)
    int s = ei[e];
    int r = ei[E + e];
    float dx = pos[r * 3 + 0] - pos[s * 3 + 0];
    float dy = pos[r * 3 + 1] - pos[s * 3 + 1];
    float dz = pos[r * 3 + 2] - pos[s * 3 + 2];
    float rr = sqrtf(dx * dx + dy * dy + dz * dz);
    float rinv = 1.0f / fmaxf(rr, 1e-9f);
    float x = dx * rinv, y = dy * rinv, z = dz * rinv;

    if (tid < 128) {
        int slot = atomicAdd(&g_cnt[r], 1);
        int p = (slot < CAP) ? (r * CAP + slot) : -1;
        sPos[el] = p;
        sSend[el] = s;
        g_pos[e] = p;
        g_send[e] = s;
        if (p >= 0) {
            float* sh = &g_shb[(size_t)p * SHP];
            *(float4*)&sh[0] = make_float4(1.0f, x, y, z);
            *(float4*)&sh[4] = make_float4(S3 * x * y, S3 * y * z,
                                           0.5f * (3.0f * z * z - 1.0f), S3 * x * z);
            *(float4*)&sh[8] = make_float4(0.5f * S3 * (x * x - y * y), 0.f, 0.f, 0.f);
        }
    }

    // radial basis: 2 thread-slices x 4 sines each
    {
        float xx = rr * (1.0f / RMAX);
        float env = 0.0f;
        if (xx < 1.0f) {
            float x2 = xx * xx, x3 = x2 * xx;
            float x6 = x3 * x3, x7 = x6 * xx, x8 = x7 * xx;
            env = 1.0f - 28.0f * x6 + 48.0f * x7 - 21.0f * x8;
        }
        float w = rr * (PI_F / RMAX);
        float pe = PREF * rinv * env;
        int j = tid >> 7;   // 0 or 1
#pragma unroll
        for (int m = 0; m < 4; m++)
            sEfT[(4 * j + m) * 128 + el] = pe * sinf((float)(4 * j + m + 1) * w);
    }
    __syncthreads();

    int eg = tid & 15;   // edge group: 8 edges
    int g2 = tid >> 4;   // hidden/channel quad

    // GEMM1: hid[el][h] = silu(b[h] + sum_k ef[el][k]*W1[k][h])
    float acc[4][8];
#pragma unroll
    for (int hi = 0; hi < 4; hi++) {
        float b = sB[g2 * 4 + hi];
#pragma unroll
        for (int ej = 0; ej < 8; ej++) acc[hi][ej] = b;
    }
#pragma unroll
    for (int k = 0; k < 8; k++) {
        float4 ea = *(const float4*)&sEfT[k * 128 + eg * 8];
        float4 eb = *(const float4*)&sEfT[k * 128 + eg * 8 + 4];
        float4 w4 = *(const float4*)&sW1[k * 64 + g2 * 4];
        float ee[8] = {ea.x, ea.y, ea.z, ea.w, eb.x, eb.y, eb.z, eb.w};
        float ww[4] = {w4.x, w4.y, w4.z, w4.w};
#pragma unroll
        for (int hi = 0; hi < 4; hi++)
#pragma unroll
            for (int ej = 0; ej < 8; ej++)
                acc[hi][ej] = fmaf(ww[hi], ee[ej], acc[hi][ej]);
    }
#pragma unroll
    for (int hi = 0; hi < 4; hi++)
#pragma unroll
        for (int ej = 0; ej < 8; ej++) {
            float a = acc[hi][ej];
            sHidT[(g2 * 4 + hi) * 128 + eg * 8 + ej] = a / (1.0f + expf(-a));
        }
    __syncthreads();

    // GEMM2: R[el][c] = sum_k hid[el][k]*W2[k][c]
#pragma unroll
    for (int ci = 0; ci < 4; ci++)
#pragma unroll
        for (int ej = 0; ej < 8; ej++) acc[ci][ej] = 0.0f;
#pragma unroll 8
    for (int k = 0; k < 64; k++) {
        float4 ha = *(const float4*)&sHidT[k * 128 + eg * 8];
        float4 hb = *(const float4*)&sHidT[k * 128 + eg * 8 + 4];
        float4 w4 = *(const float4*)&sW2[k * 64 + g2 * 4];
        float hh[8] = {ha.x, ha.y, ha.z, ha.w, hb.x, hb.y, hb.z, hb.w};
        float ww[4] = {w4.x, w4.y, w4.z, w4.w};
#pragma unroll
        for (int ci = 0; ci < 4; ci++)
#pragma unroll
            for (int ej = 0; ej < 8; ej++)
                acc[ci][ej] = fmaf(ww[ci], hh[ej], acc[ci][ej]);
    }

    // store R (fp16, for layer 1) and t0 = R * h1[send] bucket-ordered
#pragma unroll
    for (int ej = 0; ej < 8; ej++) {
        int eloc = eg * 8 + ej;
        int ee = e0 + eloc;
        __half2 p0 = __floats2half2_rn(acc[0][ej], acc[1][ej]);
        __half2 p1 = __floats2half2_rn(acc[2][ej], acc[3][ej]);
        __half2* dst = (__half2*)&g_Rh[(size_t)ee * C + g2 * 4];
        dst[0] = p0;
        dst[1] = p1;

        int p = sPos[eloc];
        if (p >= 0) {
            float4 h4 = *(const float4*)&g_h1[sSend[eloc] * C + g2 * 4];
            __half2 t0 = __floats2half2_rn(acc[0][ej] * h4.x, acc[1][ej] * h4.y);
            __half2 t1 = __floats2half2_rn(acc[2][ej] * h4.z, acc[3][ej] * h4.w);
            __half2* td = (__half2*)&g_tb[(size_t)p * C + g2 * 4];
            td[0] = t0;
            td[1] = t1;
        }
    }
}

// layer-1 t: t[pos[e]][c] = R[e][c] * h1[send[e]][c]; 8 edges/block-of-256
__global__ __launch_bounds__(256) void k_edge_t() {
    int e = blockIdx.x * 8 + (threadIdx.x >> 5);
    int lane = threadIdx.x & 31;
    int p = g_pos[e];
    if (p < 0) return;
    int s = g_send[e];
    float2 rv = __half22float2(*(const __half2*)&g_Rh[(size_t)e * C + 2 * lane]);
    float2 hv = *(const float2*)&g_h1[s * C + 2 * lane];
    *(__half2*)&g_tb[(size_t)p * C + 2 * lane] =
        __floats2half2_rn(rv.x * hv.x, rv.y * hv.y);
}

// h1 = h @ W_up, sc = h @ W_sc; 32 nodes/block, 128 threads, 4x4 blocking
__global__ __launch_bounds__(128) void k_linear(const float* __restrict__ Wup,
                                                const float* __restrict__ Wsc) {
    constexpr int TS = 36;
    __shared__ float sWu[64 * 64];
    __shared__ float sWs[64 * 64];
    __shared__ float sHT[64 * TS];

    int tid = threadIdx.x;
    int n0 = blockIdx.x * 32;
    for (int i = tid; i < 4096; i += 128) { sWu[i] = Wup[i]; sWs[i] = Wsc[i]; }
    for (int i = tid; i < 512; i += 128) {
        int nl = i >> 4, kq = i & 15;
        int n = n0 + nl;
        float4 v = (n < N) ? *(const float4*)&g_h[n * 64 + kq * 4]
                           : make_float4(0.f, 0.f, 0.f, 0.f);
        sHT[(kq * 4 + 0) * TS + nl] = v.x;
        sHT[(kq * 4 + 1) * TS + nl] = v.y;
        sHT[(kq * 4 + 2) * TS + nl] = v.z;
        sHT[(kq * 4 + 3) * TS + nl] = v.w;
    }
    __syncthreads();

    int ng = tid & 7;
    int cg = tid >> 3;
    float au[4][4], as_[4][4];
#pragma unroll
    for (int ci = 0; ci < 4; ci++)
#pragma unroll
        for (int nj = 0; nj < 4; nj++) { au[ci][nj] = 0.f; as_[ci][nj] = 0.f; }

#pragma unroll 8
    for (int k = 0; k < 64; k++) {
        float4 h4 = *(const float4*)&sHT[k * TS + ng * 4];
        float4 u4 = *(const float4*)&sWu[k * 64 + cg * 4];
        float4 s4 = *(const float4*)&sWs[k * 64 + cg * 4];
        float hh[4] = {h4.x, h4.y, h4.z, h4.w};
        float uu[4] = {u4.x, u4.y, u4.z, u4.w};
        float ss[4] = {s4.x, s4.y, s4.z, s4.w};
#pragma unroll
        for (int ci = 0; ci < 4; ci++)
#pragma unroll
            for (int nj = 0; nj < 4; nj++) {
                au[ci][nj]  = fmaf(uu[ci], hh[nj], au[ci][nj]);
                as_[ci][nj] = fmaf(ss[ci], hh[nj], as_[ci][nj]);
            }
    }
#pragma unroll
    for (int nj = 0; nj < 4; nj++) {
        int n = n0 + ng * 4 + nj;
        if (n < N) {
            *(float4*)&g_h1[n * 64 + cg * 4] =
                make_float4(au[0][nj], au[1][nj], au[2][nj], au[3][nj]);
            *(float4*)&g_sc[n * 64 + cg * 4] =
                make_float4(as_[0][nj], as_[1][nj], as_[2][nj], as_[3][nj]);
        }
    }
}

// gather: 1 warp/node, 2 ch/thread, ZERO indirection — all addresses are
// affine in the loop index (bucket-ordered sh and t). unroll-4 gives MLP.
__global__ __launch_bounds__(256) void k_gather() {
    int n = blockIdx.x * 8 + (threadIdx.x >> 5);
    int lane = threadIdx.x & 31;
    int cnt = g_cnt[n];
    if (cnt > CAP) cnt = CAP;
    size_t base = (size_t)n * CAP;
    const float*  shb = &g_shb[base * SHP];
    const __half* tb  = &g_tb[base * C + 2 * lane];

    float acc0[LM], acc1[LM];
#pragma unroll
    for (int j = 0; j < LM; j++) { acc0[j] = 0.0f; acc1[j] = 0.0f; }

#pragma unroll 4
    for (int i = 0; i < cnt; i++) {
        const float4* shp = (const float4*)&shb[i * SHP];
        float4 sa = __ldg(&shp[0]);           // uniform broadcast
        float4 sb = __ldg(&shp[1]);
        float  s8 = __ldg(&shb[i * SHP + 8]);
        float2 tv = __half22float2(*(const __half2*)&tb[i * C]);
        float shv[LM] = {sa.x, sa.y, sa.z, sa.w, sb.x, sb.y, sb.z, sb.w, s8};
#pragma unroll
        for (int j = 0; j < LM; j++) {
            acc0[j] = fmaf(shv[j], tv.x, acc0[j]);
            acc1[j] = fmaf(shv[j], tv.y, acc1[j]);
        }
    }

    float q0 = acc0[0] * INV_AVG;
    float q1 = acc1[0] * INV_AVG;
#pragma unroll
    for (int j = 0; j < LM; j++) {
        float a0 = acc0[j] * INV_AVG;
        float a1 = acc1[j] * INV_AVG;
        q0 = fmaf(a0, a0, q0);
        q1 = fmaf(a1, a1, q1);
    }
    *(float2*)&g_q[n * C + 2 * lane] = make_float2(q0, q1);
}

// h = q @ W_prod + sc; node energy -> per-graph bins. 32 nodes/block.
__global__ __launch_bounds__(128) void k_update(const float* __restrict__ Wp,
                                                const float* __restrict__ wro,
                                                const int* __restrict__ batch,
                                                float* __restrict__ out) {
    constexpr int TS = 36;
    __shared__ float sWp[64 * 64];
    __shared__ float sQT[64 * TS];
    __shared__ float sE[32];

    int tid = threadIdx.x;
    int n0 = blockIdx.x * 32;
    for (int i = tid; i < 4096; i += 128) sWp[i] = Wp[i];
    if (tid < 32) sE[tid] = 0.0f;
    for (int i = tid; i < 512; i += 128) {
        int nl = i >> 4, kq = i & 15;
        int n = n0 + nl;
        float4 v = (n < N) ? *(const float4*)&g_q[n * 64 + kq * 4]
                           : make_float4(0.f, 0.f, 0.f, 0.f);
        sQT[(kq * 4 + 0) * TS + nl] = v.x;
        sQT[(kq * 4 + 1) * TS + nl] = v.y;
        sQT[(kq * 4 + 2) * TS + nl] = v.z;
        sQT[(kq * 4 + 3) * TS + nl] = v.w;
    }
    __syncthreads();

    int ng = tid & 7;
    int cg = tid >> 3;
    float acc[4][4];
#pragma unroll
    for (int ci = 0; ci < 4; ci++)
#pragma unroll
        for (int nj = 0; nj < 4; nj++) acc[ci][nj] = 0.f;

#pragma unroll 8
    for (int k = 0; k < 64; k++) {
        float4 q4 = *(const float4*)&sQT[k * TS + ng * 4];
        float4 w4 = *(const float4*)&sWp[k * 64 + cg * 4];
        float qq[4] = {q4.x, q4.y, q4.z, q4.w};
        float ww[4] = {w4.x, w4.y, w4.z, w4.w};
#pragma unroll
        for (int ci = 0; ci < 4; ci++)
#pragma unroll
            for (int nj = 0; nj < 4; nj++)
                acc[ci][nj] = fmaf(ww[ci], qq[nj], acc[ci][nj]);
    }

    float4 wr4 = *(const float4*)&wro[cg * 4];
    float wr[4] = {wr4.x, wr4.y, wr4.z, wr4.w};
#pragma unroll
    for (int nj = 0; nj < 4; nj++) {
        int n = n0 + ng * 4 + nj;
        if (n < N) {
            float4 sc4 = *(const float4*)&g_sc[n * 64 + cg * 4];
            float hn[4] = {acc[0][nj] + sc4.x, acc[1][nj] + sc4.y,
                           acc[2][nj] + sc4.z, acc[3][nj] + sc4.w};
            *(float4*)&g_h[n * 64 + cg * 4] =
                make_float4(hn[0], hn[1], hn[2], hn[3]);
            float p = hn[0] * wr[0] + hn[1] * wr[1] + hn[2] * wr[2] + hn[3] * wr[3];
            atomicAdd(&sE[ng * 4 + nj], p);
        }
    }
    __syncthreads();
    if (tid < 32) {
        int n = n0 + tid;
        if (n < N) atomicAdd(&out[batch[n]], sE[tid]);
    }
}

// ---------------- launcher ----------------
extern "C" void kernel_launch(void* const* d_in, const int* in_sizes, int n_in,
                              void* d_out, int out_size) {
    const float* pos     = (const float*)d_in[0];
    const float* W_embed = (const float*)d_in[1];
    const float* W_r1    = (const float*)d_in[2];
    const float* b_r1    = (const float*)d_in[3];
    const float* W_r2    = (const float*)d_in[4];
    const float* W_up    = (const float*)d_in[5];
    const float* W_sc    = (const float*)d_in[6];
    const float* W_prod  = (const float*)d_in[7];
    const float* w_ro    = (const float*)d_in[8];
    const int*   types   = (const int*)d_in[9];
    const int*   ei      = (const int*)d_in[10];
    const int*   batch   = (const int*)d_in[11];
    float* out = (float*)d_out;

    k_prep<<<(N * C + 255) / 256, 256>>>(W_embed, types, out, out_size);
    // layer-0 h1/sc must exist before k_edge_radial (it fuses t0 = R*h1[send])
    k_linear<<<(N + 31) / 32, 128>>>(W_up, W_sc);
    k_edge_radial<<<E / 128, 256>>>(pos, ei, W_r1, b_r1, W_r2);

    k_gather<<<N / 8, 256>>>();
    k_update<<<(N + 31) / 32, 128>>>(W_prod, w_ro, batch, out);

    k_linear<<<(N + 31) / 32, 128>>>(W_up + C * C, W_sc + C * C);
    k_edge_t<<<E / 8, 256>>>();
    k_gather<<<N / 8, 256>>>();
    k_update<<<(N + 31) / 32, 128>>>(W_prod + C * C, w_ro + C, batch, out);
}

// round 8
// speedup vs baseline: 1.2454x; 1.2454x over previous
#include <cuda_runtime.h>
#include <cuda_fp16.h>
#include <math.h>

// ---------------- problem constants ----------------
namespace {
constexpr int N   = 10000;
constexpr int E   = 160000;
constexpr int C   = 64;
constexpr int LM  = 9;
constexpr int CAP = 64;          // bucket capacity (max degree ~40 for Poisson(16))
constexpr float RMAX    = 5.0f;
constexpr float INV_AVG = 1.0f / 16.0f;
constexpr float S3      = 1.7320508f;
constexpr float PI_F    = 3.14159265358979f;
constexpr float PREF    = 0.63245553203f; // sqrt(2/RMAX)
}

// ---------------- device scratch (static, no allocation) ----------------
__device__ float  g_h [N * C];
__device__ float  g_h1[N * C];
__device__ float  g_sc[N * C];
__device__ float  g_q [N * C];
__device__ float4 g_u [E];                 // unit edge vector (x,y,z,-)
__device__ __half g_Rh[(size_t)E * C];
__device__ int    g_cnt[N];
__device__ int2   g_bkt[(size_t)N * CAP];  // (edge, sender) per receiver slot

// ---------------- kernels ----------------

// zero counters + output bins, embed h
__global__ void k_prep(const float* __restrict__ W_embed,
                       const int* __restrict__ types,
                       float* __restrict__ out, int out_size) {
    int i = blockIdx.x * blockDim.x + threadIdx.x;
    if (i < N * C) {
        int n = i >> 6, c = i & 63;
        g_h[i] = W_embed[types[n] * C + c];
    }
    if (i < N) g_cnt[i] = 0;
    if (i < out_size) out[i] = 0.0f;
}

// Fused: per-edge geometry (u vector + bucket scatter), radial Bessel basis,
// radial MLP R = silu(ef@W1+b)@W2 stored fp16.
// 256 threads handle 128 edges; 4x8 register-blocked GEMMs.
__global__ __launch_bounds__(256) void k_edge_radial(
    const float* __restrict__ pos, const int* __restrict__ ei,
    const float* __restrict__ W1, const float* __restrict__ b1,
    const float* __restrict__ W2)
{
    __shared__ float sW1[8 * 64];
    __shared__ float sB[64];
    __shared__ float sW2[64 * 64];
    __shared__ float sEfT[8 * 128];     // [k][edge]
    __shared__ float sHidT[64 * 128];   // [hidden][edge]

    int tid = threadIdx.x;
    int e0 = blockIdx.x * 128;
    int el = tid & 127;
    int e = e0 + el;

    for (int i = tid; i < 512; i += 256) sW1[i] = W1[i];
    if (tid < 64) sB[tid] = b1[tid];
    for (int i = tid; i < 4096; i += 256) sW2[i] = W2[i];

    // geometry (computed redundantly by the 2 thread-slices; cheap)
    int s = ei[e];
    int r = ei[E + e];
    float dx = pos[r * 3 + 0] - pos[s * 3 + 0];
    float dy = pos[r * 3 + 1] - pos[s * 3 + 1];
    float dz = pos[r * 3 + 2] - pos[s * 3 + 2];
    float rr = sqrtf(dx * dx + dy * dy + dz * dz);
    float rinv = 1.0f / fmaxf(rr, 1e-9f);
    float x = dx * rinv, y = dy * rinv, z = dz * rinv;

    if (tid < 128) {
        g_u[e] = make_float4(x, y, z, 0.0f);
        int slot = atomicAdd(&g_cnt[r], 1);
        if (slot < CAP) g_bkt[(size_t)r * CAP + slot] = make_int2(e, s);
    }

    // radial basis: 2 thread-slices x 4 sines each
    {
        float xx = rr * (1.0f / RMAX);
        float env = 0.0f;
        if (xx < 1.0f) {
            float x2 = xx * xx, x3 = x2 * xx;
            float x6 = x3 * x3, x7 = x6 * xx, x8 = x7 * xx;
            env = 1.0f - 28.0f * x6 + 48.0f * x7 - 21.0f * x8;
        }
        float w = rr * (PI_F / RMAX);
        float pe = PREF * rinv * env;
        int j = tid >> 7;   // 0 or 1
#pragma unroll
        for (int m = 0; m < 4; m++)
            sEfT[(4 * j + m) * 128 + el] = pe * sinf((float)(4 * j + m + 1) * w);
    }
    __syncthreads();

    int eg = tid & 15;   // edge group: 8 edges
    int g2 = tid >> 4;   // hidden/channel quad

    // GEMM1: hid[el][h] = silu(b[h] + sum_k ef[el][k]*W1[k][h])
    float acc[4][8];
#pragma unroll
    for (int hi = 0; hi < 4; hi++) {
        float b = sB[g2 * 4 + hi];
#pragma unroll
        for (int ej = 0; ej < 8; ej++) acc[hi][ej] = b;
    }
#pragma unroll
    for (int k = 0; k < 8; k++) {
        float4 ea = *(const float4*)&sEfT[k * 128 + eg * 8];
        float4 eb = *(const float4*)&sEfT[k * 128 + eg * 8 + 4];
        float4 w4 = *(const float4*)&sW1[k * 64 + g2 * 4];
        float ee[8] = {ea.x, ea.y, ea.z, ea.w, eb.x, eb.y, eb.z, eb.w};
        float ww[4] = {w4.x, w4.y, w4.z, w4.w};
#pragma unroll
        for (int hi = 0; hi < 4; hi++)
#pragma unroll
            for (int ej = 0; ej < 8; ej++)
                acc[hi][ej] = fmaf(ww[hi], ee[ej], acc[hi][ej]);
    }
#pragma unroll
    for (int hi = 0; hi < 4; hi++)
#pragma unroll
        for (int ej = 0; ej < 8; ej++) {
            float a = acc[hi][ej];
            sHidT[(g2 * 4 + hi) * 128 + eg * 8 + ej] = a / (1.0f + expf(-a));
        }
    __syncthreads();

    // GEMM2: R[el][c] = sum_k hid[el][k]*W2[k][c]
#pragma unroll
    for (int ci = 0; ci < 4; ci++)
#pragma unroll
        for (int ej = 0; ej < 8; ej++) acc[ci][ej] = 0.0f;
#pragma unroll 8
    for (int k = 0; k < 64; k++) {
        float4 ha = *(const float4*)&sHidT[k * 128 + eg * 8];
        float4 hb = *(const float4*)&sHidT[k * 128 + eg * 8 + 4];
        float4 w4 = *(const float4*)&sW2[k * 64 + g2 * 4];
        float hh[8] = {ha.x, ha.y, ha.z, ha.w, hb.x, hb.y, hb.z, hb.w};
        float ww[4] = {w4.x, w4.y, w4.z, w4.w};
#pragma unroll
        for (int ci = 0; ci < 4; ci++)
#pragma unroll
            for (int ej = 0; ej < 8; ej++)
                acc[ci][ej] = fmaf(ww[ci], hh[ej], acc[ci][ej]);
    }
#pragma unroll
    for (int ej = 0; ej < 8; ej++) {
        int ee = e0 + eg * 8 + ej;
        __half2 p0 = __floats2half2_rn(acc[0][ej], acc[1][ej]);
        __half2 p1 = __floats2half2_rn(acc[2][ej], acc[3][ej]);
        __half2* dst = (__half2*)&g_Rh[(size_t)ee * C + g2 * 4];
        dst[0] = p0;
        dst[1] = p1;
    }
}

// h1 = h @ W_up, sc = h @ W_sc; 32 nodes/block, 128 threads, 4x4 blocking
__global__ __launch_bounds__(128) void k_linear(const float* __restrict__ Wup,
                                                const float* __restrict__ Wsc) {
    constexpr int TS = 36;
    __shared__ float sWu[64 * 64];
    __shared__ float sWs[64 * 64];
    __shared__ float sHT[64 * TS];

    int tid = threadIdx.x;
    int n0 = blockIdx.x * 32;
    for (int i = tid; i < 4096; i += 128) { sWu[i] = Wup[i]; sWs[i] = Wsc[i]; }
    for (int i = tid; i < 512; i += 128) {
        int nl = i >> 4, kq = i & 15;
        int n = n0 + nl;
        float4 v = (n < N) ? *(const float4*)&g_h[n * 64 + kq * 4]
                           : make_float4(0.f, 0.f, 0.f, 0.f);
        sHT[(kq * 4 + 0) * TS + nl] = v.x;
        sHT[(kq * 4 + 1) * TS + nl] = v.y;
        sHT[(kq * 4 + 2) * TS + nl] = v.z;
        sHT[(kq * 4 + 3) * TS + nl] = v.w;
    }
    __syncthreads();

    int ng = tid & 7;
    int cg = tid >> 3;
    float au[4][4], as_[4][4];
#pragma unroll
    for (int ci = 0; ci < 4; ci++)
#pragma unroll
        for (int nj = 0; nj < 4; nj++) { au[ci][nj] = 0.f; as_[ci][nj] = 0.f; }

#pragma unroll 8
    for (int k = 0; k < 64; k++) {
        float4 h4 = *(const float4*)&sHT[k * TS + ng * 4];
        float4 u4 = *(const float4*)&sWu[k * 64 + cg * 4];
        float4 s4 = *(const float4*)&sWs[k * 64 + cg * 4];
        float hh[4] = {h4.x, h4.y, h4.z, h4.w};
        float uu[4] = {u4.x, u4.y, u4.z, u4.w};
        float ss[4] = {s4.x, s4.y, s4.z, s4.w};
#pragma unroll
        for (int ci = 0; ci < 4; ci++)
#pragma unroll
            for (int nj = 0; nj < 4; nj++) {
                au[ci][nj]  = fmaf(uu[ci], hh[nj], au[ci][nj]);
                as_[ci][nj] = fmaf(ss[ci], hh[nj], as_[ci][nj]);
            }
    }
#pragma unroll
    for (int nj = 0; nj < 4; nj++) {
        int n = n0 + ng * 4 + nj;
        if (n < N) {
            *(float4*)&g_h1[n * 64 + cg * 4] =
                make_float4(au[0][nj], au[1][nj], au[2][nj], au[3][nj]);
            *(float4*)&g_sc[n * 64 + cg * 4] =
                make_float4(as_[0][nj], as_[1][nj], as_[2][nj], as_[3][nj]);
        }
    }
}

// gather: 4 nodes/block, 2 warps per node (edge-interleaved), 2 ch/thread.
// The bucket is preloaded into registers (1 coalesced load), so every loop
// iteration's edge/sender come from SHUFFLES (ALU) and all load addresses
// are ready immediately -> deep MLP. sh rebuilt per-thread from u (float4).
__global__ __launch_bounds__(256) void k_gather() {
    __shared__ float sPart[4][LM][64];   // parity-1 warp partials

    int nl   = threadIdx.x >> 6;         // node slot in block (0..3)
    int n    = blockIdx.x * 4 + nl;
    int p    = (threadIdx.x >> 5) & 1;   // parity warp: edges p, p+2, ...
    int lane = threadIdx.x & 31;
    int cnt  = g_cnt[n];
    if (cnt > CAP) cnt = CAP;
    const int2* bkt = &g_bkt[(size_t)n * CAP];

    // preload bucket entries: lane i holds slots i and i+32
    int2 my0 = __ldg(&bkt[lane]);
    int2 my1 = __ldg(&bkt[lane + 32]);

    float acc0[LM], acc1[LM];
#pragma unroll
    for (int j = 0; j < LM; j++) { acc0[j] = 0.0f; acc1[j] = 0.0f; }

#pragma unroll 4
    for (int i = p; i < cnt; i += 2) {
        int src = i & 31;
        int ex = (i < 32) ? my0.x : my1.x;   // uniform select, then shuffle
        int sx = (i < 32) ? my0.y : my1.y;
        int e = __shfl_sync(0xffffffffu, ex, src);
        int s = __shfl_sync(0xffffffffu, sx, src);

        float4 u4 = __ldg(&g_u[e]);          // uniform broadcast, 16B
        float2 rv = __half22float2(*(const __half2*)&g_Rh[(size_t)e * C + 2 * lane]);
        float2 hv = *(const float2*)&g_h1[s * C + 2 * lane];

        float x = u4.x, y = u4.y, z = u4.z;
        float shv[LM] = {1.0f, x, y, z,
                         S3 * x * y, S3 * y * z,
                         0.5f * (3.0f * z * z - 1.0f), S3 * x * z,
                         0.5f * S3 * (x * x - y * y)};
        float t0 = rv.x * hv.x;
        float t1 = rv.y * hv.y;
#pragma unroll
        for (int j = 0; j < LM; j++) {
            acc0[j] = fmaf(shv[j], t0, acc0[j]);
            acc1[j] = fmaf(shv[j], t1, acc1[j]);
        }
    }

    if (p == 1) {
#pragma unroll
        for (int j = 0; j < LM; j++) {
            sPart[nl][j][2 * lane]     = acc0[j];
            sPart[nl][j][2 * lane + 1] = acc1[j];
        }
    }
    __syncthreads();
    if (p == 0) {
        float q0 = 0.0f, q1 = 0.0f;
#pragma unroll
        for (int j = 0; j < LM; j++) {
            float a0 = (acc0[j] + sPart[nl][j][2 * lane])     * INV_AVG;
            float a1 = (acc1[j] + sPart[nl][j][2 * lane + 1]) * INV_AVG;
            if (j == 0) { q0 = a0; q1 = a1; }
            q0 = fmaf(a0, a0, q0);
            q1 = fmaf(a1, a1, q1);
        }
        *(float2*)&g_q[n * C + 2 * lane] = make_float2(q0, q1);
    }
}

// h = q @ W_prod + sc; node energy -> per-graph bins. 32 nodes/block.
__global__ __launch_bounds__(128) void k_update(const float* __restrict__ Wp,
                                                const float* __restrict__ wro,
                                                const int* __restrict__ batch,
                                                float* __restrict__ out) {
    constexpr int TS = 36;
    __shared__ float sWp[64 * 64];
    __shared__ float sQT[64 * TS];
    __shared__ float sE[32];

    int tid = threadIdx.x;
    int n0 = blockIdx.x * 32;
    for (int i = tid; i < 4096; i += 128) sWp[i] = Wp[i];
    if (tid < 32) sE[tid] = 0.0f;
    for (int i = tid; i < 512; i += 128) {
        int nl = i >> 4, kq = i & 15;
        int n = n0 + nl;
        float4 v = (n < N) ? *(const float4*)&g_q[n * 64 + kq * 4]
                           : make_float4(0.f, 0.f, 0.f, 0.f);
        sQT[(kq * 4 + 0) * TS + nl] = v.x;
        sQT[(kq * 4 + 1) * TS + nl] = v.y;
        sQT[(kq * 4 + 2) * TS + nl] = v.z;
        sQT[(kq * 4 + 3) * TS + nl] = v.w;
    }
    __syncthreads();

    int ng = tid & 7;
    int cg = tid >> 3;
    float acc[4][4];
#pragma unroll
    for (int ci = 0; ci < 4; ci++)
#pragma unroll
        for (int nj = 0; nj < 4; nj++) acc[ci][nj] = 0.f;

#pragma unroll 8
    for (int k = 0; k < 64; k++) {
        float4 q4 = *(const float4*)&sQT[k * TS + ng * 4];
        float4 w4 = *(const float4*)&sWp[k * 64 + cg * 4];
        float qq[4] = {q4.x, q4.y, q4.z, q4.w};
        float ww[4] = {w4.x, w4.y, w4.z, w4.w};
#pragma unroll
        for (int ci = 0; ci < 4; ci++)
#pragma unroll
            for (int nj = 0; nj < 4; nj++)
                acc[ci][nj] = fmaf(ww[ci], qq[nj], acc[ci][nj]);
    }

    float4 wr4 = *(const float4*)&wro[cg * 4];
    float wr[4] = {wr4.x, wr4.y, wr4.z, wr4.w};
#pragma unroll
    for (int nj = 0; nj < 4; nj++) {
        int n = n0 + ng * 4 + nj;
        if (n < N) {
            float4 sc4 = *(const float4*)&g_sc[n * 64 + cg * 4];
            float hn[4] = {acc[0][nj] + sc4.x, acc[1][nj] + sc4.y,
                           acc[2][nj] + sc4.z, acc[3][nj] + sc4.w};
            *(float4*)&g_h[n * 64 + cg * 4] =
                make_float4(hn[0], hn[1], hn[2], hn[3]);
            float p = hn[0] * wr[0] + hn[1] * wr[1] + hn[2] * wr[2] + hn[3] * wr[3];
            atomicAdd(&sE[ng * 4 + nj], p);
        }
    }
    __syncthreads();
    if (tid < 32) {
        int n = n0 + tid;
        if (n < N) atomicAdd(&out[batch[n]], sE[tid]);
    }
}

// ---------------- launcher ----------------
extern "C" void kernel_launch(void* const* d_in, const int* in_sizes, int n_in,
                              void* d_out, int out_size) {
    const float* pos     = (const float*)d_in[0];
    const float* W_embed = (const float*)d_in[1];
    const float* W_r1    = (const float*)d_in[2];
    const float* b_r1    = (const float*)d_in[3];
    const float* W_r2    = (const float*)d_in[4];
    const float* W_up    = (const float*)d_in[5];
    const float* W_sc    = (const float*)d_in[6];
    const float* W_prod  = (const float*)d_in[7];
    const float* w_ro    = (const float*)d_in[8];
    const int*   types   = (const int*)d_in[9];
    const int*   ei      = (const int*)d_in[10];
    const int*   batch   = (const int*)d_in[11];
    float* out = (float*)d_out;

    k_prep<<<(N * C + 255) / 256, 256>>>(W_embed, types, out, out_size);
    k_edge_radial<<<E / 128, 256>>>(pos, ei, W_r1, b_r1, W_r2);

    for (int l = 0; l < 2; l++) {
        k_linear<<<(N + 31) / 32, 128>>>(W_up + l * C * C, W_sc + l * C * C);
        k_gather<<<N / 4, 256>>>();
        k_update<<<(N + 31) / 32, 128>>>(W_prod + l * C * C, w_ro + l * C, batch, out);
    }
}